// round 8
// baseline (speedup 1.0000x reference)
#include <cuda_runtime.h>
#include <cuda_bf16.h>
#include <cstdint>
#include <math.h>

// ---------------------------------------------------------------------------
// ActorMultiHead — tf32 mma.sync pipeline, 3-stage cp.async double buffering.
// (tcgen05 is unavailable: harness PTX target is sm_103 without the 'a'
//  feature set, so all tcgen05.* are rejected by ptxas.)
//
//   pack_x : Xp[32768,160] = tf32(concat(obs, onehot(role,2)), zero-pad)
//   pack_w : wp = tf32({W0 padded to [160,1024], W1, W2, hW1 repacked})
//   gemm x4: 128x128 CTA tile, BK=32, 4 warps (64x64 warp tile),
//            THREE-stage cp.async pipeline, ONE syncthreads per k-tile,
//            m16n8k8 tf32 mma, bias+relu(+round) epilogue
//   head2  : per-token head-2 matvec + tanh + Gaussian log-prob
// ---------------------------------------------------------------------------

#define M_TOTAL  32768
#define BM 128
#define BN 128
#define BK 32
#define AS_STRIDE 36           // 36 ≡ 4 (mod 32): conflict-free A frag LDS
#define BS_STRIDE 136          // 136 ≡ 8 (mod 32): conflict-free B frag LDS
#define ASZ (BM * AS_STRIDE)   // 4608 floats
#define BSZ (BK * BS_STRIDE)   // 4352 floats
#define STG (ASZ + BSZ)        // 8960 floats per stage
#define NSTAGE 3
#define SMEM_BYTES (NSTAGE * STG * 4)   // 107520 B

#define W0P_OFF 0
#define W1_OFF  (160 * 1024)
#define W2_OFF  (W1_OFF + 1024 * 1024)
#define HW1_OFF (W2_OFF + 1024 * 1024)
#define WP_TOTAL (HW1_OFF + 1024 * 1024)

// Scratch (allocation-free __device__ globals)
__device__ float g_bufA[M_TOTAL * 1024];
__device__ float g_bufB[M_TOTAL * 1024];
__device__ float g_xpad[M_TOTAL * 160];
__device__ float g_wp[WP_TOTAL];

__device__ __forceinline__ float tf32_round(float f) {
    unsigned u;
    asm("cvt.rna.tf32.f32 %0, %1;" : "=r"(u) : "f"(f));
    return __uint_as_float(u);
}

__device__ __forceinline__ void mma_tf32(float d[4], const unsigned a[4], const unsigned b[2]) {
    asm("mma.sync.aligned.m16n8k8.row.col.f32.tf32.tf32.f32 "
        "{%0,%1,%2,%3}, {%4,%5,%6,%7}, {%8,%9}, {%0,%1,%2,%3};\n"
        : "+f"(d[0]), "+f"(d[1]), "+f"(d[2]), "+f"(d[3])
        : "r"(a[0]), "r"(a[1]), "r"(a[2]), "r"(a[3]), "r"(b[0]), "r"(b[1]));
}

__device__ __forceinline__ void cp16(unsigned s, const float* g) {
    asm volatile("cp.async.cg.shared.global [%0], [%1], 16;\n" :: "r"(s), "l"(g));
}

// ---------------------------------------------------------------------------
// Prepack kernels
// ---------------------------------------------------------------------------
__global__ void pack_x(const float* __restrict__ obs, const int* __restrict__ roles,
                       float* __restrict__ xp)
{
    const int t = blockIdx.x;
    const int k = threadIdx.x;          // 0..159
    float v = 0.f;
    if (k < 128)      v = obs[t * 128 + k];
    else if (k < 130) v = (roles[t] == (k - 128)) ? 1.f : 0.f;
    xp[t * 160 + k] = tf32_round(v);
}

__global__ void pack_w(const float* __restrict__ W0, const float* __restrict__ W1,
                       const float* __restrict__ W2, const float* __restrict__ hW1,
                       float* __restrict__ wp)
{
    const int idx = blockIdx.x * 256 + threadIdx.x;
    if (idx >= WP_TOTAL) return;
    float v;
    if (idx < W1_OFF) {                        // W0 padded [160,1024]
        int k = idx >> 10, n = idx & 1023;
        v = (k < 130) ? W0[k * 1024 + n] : 0.f;
    } else if (idx < W2_OFF) {
        v = W1[idx - W1_OFF];
    } else if (idx < HW1_OFF) {
        v = W2[idx - W2_OFF];
    } else {                                   // hW1 [2,1024,512] -> [1024,1024]
        int j = idx - HW1_OFF;
        int k = j >> 10, n = j & 1023;
        int r = n >> 9, c = n & 511;
        v = hW1[r * (1024 * 512) + k * 512 + c];
    }
    wp[idx] = tf32_round(v);
}

// ---------------------------------------------------------------------------
// GEMM: C[M,1024] = relu(A[M,K] @ B[K,1024] + bias), data pre-rounded tf32.
// 128 threads, 4 warps (2x2), warp tile 64x64, 3-stage cp.async pipeline.
// ---------------------------------------------------------------------------
template <int ROUND>
__global__ void __launch_bounds__(128, 2)
gemm_tc(const float* __restrict__ A, const float* __restrict__ B,
        const float* __restrict__ bias, float* __restrict__ C, int K)
{
    extern __shared__ float smem[];
    const int tid  = threadIdx.x;
    const int lane = tid & 31;
    const int warp = tid >> 5;
    const int wm = warp >> 1;            // 2 warps along M
    const int wn = warp & 1;             // 2 warps along N
    const int blockM = blockIdx.y * BM;
    const int blockN = blockIdx.x * BN;

    const unsigned smemB = (unsigned)__cvta_generic_to_shared(smem);

    // staging thread-invariants: A = 1024 f4 (8/thread), B = 1024 f4 (8/thread)
    const int aRow = tid >> 3, aC = (tid & 7) * 4;
    const int bRow = tid >> 5, bC = (tid & 31) * 4;
    const float* aG0 = A + (blockM + aRow) * K + aC;
    const float* bG0 = B + bRow * 1024 + blockN + bC;
    const unsigned aS0 = smemB + (unsigned)(aRow * AS_STRIDE + aC) * 4u;
    const unsigned bS0 = smemB + (unsigned)(ASZ + bRow * BS_STRIDE + bC) * 4u;

    auto stage = [&](int kt) {
        const unsigned so = (unsigned)(kt % NSTAGE) * (STG * 4u);
        const float* ag = aG0 + kt * BK;
        const float* bg = bG0 + kt * BK * 1024;
#pragma unroll
        for (int i = 0; i < 8; i++)
            cp16(aS0 + so + (unsigned)(i * 16 * AS_STRIDE * 4), ag + i * 16 * K);
#pragma unroll
        for (int i = 0; i < 8; i++)
            cp16(bS0 + so + (unsigned)(i * 4 * BS_STRIDE * 4), bg + i * 4 * 1024);
        asm volatile("cp.async.commit_group;\n");
    };

    float acc[4][8][4];
#pragma unroll
    for (int mi = 0; mi < 4; mi++)
#pragma unroll
        for (int ni = 0; ni < 8; ni++)
#pragma unroll
            for (int c = 0; c < 4; c++) acc[mi][ni][c] = 0.f;

    const int T = K >> 5;
    stage(0);
    if (T > 1) stage(1);

    for (int t = 0; t < T; t++) {
        // make group t's data resident (keep up to 1 newer group in flight)
        if (t + 1 < T) asm volatile("cp.async.wait_group 1;\n" ::: "memory");
        else           asm volatile("cp.async.wait_group 0;\n" ::: "memory");
        __syncthreads();   // cross-thread visibility of buf t%3 AND all warps
                           // done reading buf (t+2)%3 (last used at iter t-1)
        if (t + 2 < T) stage(t + 2);

        const float* as = smem + (t % NSTAGE) * STG;
        const float* bs = as + ASZ;

#pragma unroll
        for (int ks = 0; ks < BK / 8; ks++) {
            unsigned a[4][4], b[8][2];
            const int ac = ks * 8 + (lane & 3);
#pragma unroll
            for (int mi = 0; mi < 4; mi++) {
                const int ar = wm * 64 + mi * 16 + (lane >> 2);
                a[mi][0] = __float_as_uint(as[ar * AS_STRIDE + ac]);
                a[mi][1] = __float_as_uint(as[(ar + 8) * AS_STRIDE + ac]);
                a[mi][2] = __float_as_uint(as[ar * AS_STRIDE + ac + 4]);
                a[mi][3] = __float_as_uint(as[(ar + 8) * AS_STRIDE + ac + 4]);
            }
            const int br  = ks * 8 + (lane & 3);
            const int bc0 = wn * 64 + (lane >> 2);
#pragma unroll
            for (int ni = 0; ni < 8; ni++) {
                b[ni][0] = __float_as_uint(bs[br * BS_STRIDE + bc0 + ni * 8]);
                b[ni][1] = __float_as_uint(bs[(br + 4) * BS_STRIDE + bc0 + ni * 8]);
            }
#pragma unroll
            for (int mi = 0; mi < 4; mi++)
#pragma unroll
                for (int ni = 0; ni < 8; ni++)
                    mma_tf32(acc[mi][ni], a[mi], b[ni]);
        }
    }

    // epilogue: bias + relu (+ tf32 round for inter-layer activations)
#pragma unroll
    for (int ni = 0; ni < 8; ni++) {
        const int col = blockN + wn * 64 + ni * 8 + 2 * (lane & 3);
        const float bb0 = bias[col];
        const float bb1 = bias[col + 1];
#pragma unroll
        for (int mi = 0; mi < 4; mi++) {
            const int row = blockM + wm * 64 + mi * 16 + (lane >> 2);
            float v0 = fmaxf(acc[mi][ni][0] + bb0, 0.f);
            float v1 = fmaxf(acc[mi][ni][1] + bb1, 0.f);
            float v2 = fmaxf(acc[mi][ni][2] + bb0, 0.f);
            float v3 = fmaxf(acc[mi][ni][3] + bb1, 0.f);
            if (ROUND) {
                v0 = tf32_round(v0); v1 = tf32_round(v1);
                v2 = tf32_round(v2); v3 = tf32_round(v3);
            }
            *(float2*)&C[row * 1024 + col]       = make_float2(v0, v1);
            *(float2*)&C[(row + 8) * 1024 + col] = make_float2(v2, v3);
        }
    }
}

// ---------------------------------------------------------------------------
// Head layer 2 + tanh + diagonal-Gaussian log prob, role-selected.
// ---------------------------------------------------------------------------
__global__ void __launch_bounds__(256)
head2_logprob_kernel(const float* __restrict__ Z,        // [32768,1024]
                     const int*   __restrict__ role_ids, // [32768]
                     const float* __restrict__ actions,  // [32768,8]
                     const float* __restrict__ hW2,      // [2*512*8]
                     const float* __restrict__ hb2,      // [16]
                     const float* __restrict__ logstd,   // [16]
                     float* __restrict__ out)            // [32768]
{
    __shared__ float sW[2 * 8 * 512];  // [r][k][m]
    __shared__ float sb[16];
    __shared__ float sls[16];

    const int tid = threadIdx.x;
    for (int idx = tid; idx < 8192; idx += 256) {
        int r = idx >> 12, rem = idx & 4095, m = rem >> 3, k = rem & 7;
        sW[r * 4096 + k * 512 + m] = hW2[idx];
    }
    if (tid < 16) { sb[tid] = hb2[tid]; sls[tid] = logstd[tid]; }
    __syncthreads();

    const int warp = tid >> 5, lane = tid & 31;
    const int t = blockIdx.x * 8 + warp;

    const int role = role_ids[t];
    if (role >= 2) { if (lane == 0) out[t] = 0.f; return; }

    const float* z = Z + (size_t)t * 1024 + role * 512;
    const float* w = sW + role * 4096;

    float s[8];
#pragma unroll
    for (int k = 0; k < 8; k++) s[k] = 0.f;
#pragma unroll
    for (int j = 0; j < 16; j++) {
        int m = lane + j * 32;
        float zv = z[m];
#pragma unroll
        for (int k = 0; k < 8; k++) s[k] += zv * w[k * 512 + m];
    }
#pragma unroll
    for (int k = 0; k < 8; k++)
#pragma unroll
        for (int off = 16; off; off >>= 1)
            s[k] += __shfl_xor_sync(0xffffffffu, s[k], off);

    if (lane == 0) {
        float lp = 0.f;
#pragma unroll
        for (int k = 0; k < 8; k++) {
            float mean = tanhf(s[k] + sb[role * 8 + k]);
            float ls = sls[role * 8 + k];
            float d = (actions[t * 8 + k] - mean) * expf(-ls);
            lp += -0.5f * d * d - ls - 0.91893853320467274178f; // 0.5*ln(2*pi)
        }
        out[t] = lp;
    }
}

extern "C" void kernel_launch(void* const* d_in, const int* in_sizes, int n_in,
                              void* d_out, int out_size)
{
    const float* obs      = (const float*)d_in[0];
    const int*   role_ids = (const int*)  d_in[1];
    const float* actions  = (const float*)d_in[2];
    const float* W0  = (const float*)d_in[3];
    const float* b0  = (const float*)d_in[4];
    const float* W1  = (const float*)d_in[5];
    const float* b1  = (const float*)d_in[6];
    const float* W2  = (const float*)d_in[7];
    const float* b2  = (const float*)d_in[8];
    const float* hW1 = (const float*)d_in[9];
    const float* hb1 = (const float*)d_in[10];  // [2,512] = flat [1024] bias
    const float* hW2 = (const float*)d_in[11];
    const float* hb2 = (const float*)d_in[12];
    const float* lsd = (const float*)d_in[13];
    float* out = (float*)d_out;

    float *bufA = nullptr, *bufB = nullptr, *xpad = nullptr, *wp = nullptr;
    cudaGetSymbolAddress((void**)&bufA, g_bufA);
    cudaGetSymbolAddress((void**)&bufB, g_bufB);
    cudaGetSymbolAddress((void**)&xpad, g_xpad);
    cudaGetSymbolAddress((void**)&wp,   g_wp);

    cudaFuncSetAttribute(gemm_tc<1>, cudaFuncAttributeMaxDynamicSharedMemorySize, SMEM_BYTES);
    cudaFuncSetAttribute(gemm_tc<0>, cudaFuncAttributeMaxDynamicSharedMemorySize, SMEM_BYTES);

    // prepack (tf32 rounding hoisted out of GEMM mainloops)
    pack_x<<<M_TOTAL, 160>>>(obs, role_ids, xpad);
    pack_w<<<(WP_TOTAL + 255) / 256, 256>>>(W0, W1, W2, hW1, wp);

    dim3 block(128);
    dim3 grid(1024 / BN, M_TOTAL / BM);   // (8, 256)

    // L0: relu(Xp @ W0p + b0)            -> bufA   (K=160)
    gemm_tc<1><<<grid, block, SMEM_BYTES>>>(xpad, wp + W0P_OFF, b0, bufA, 160);
    // L1: relu(bufA @ W1 + b1)           -> bufB
    gemm_tc<1><<<grid, block, SMEM_BYTES>>>(bufA, wp + W1_OFF, b1, bufB, 1024);
    // L2: relu(bufB @ W2 + b2)           -> bufA
    gemm_tc<1><<<grid, block, SMEM_BYTES>>>(bufB, wp + W2_OFF, b2, bufA, 1024);
    // heads L1 (roles stacked along N): relu(bufA @ hW1p + hb1) -> bufB (no round)
    gemm_tc<0><<<grid, block, SMEM_BYTES>>>(bufA, wp + HW1_OFF, hb1, bufB, 1024);
    // head L2 + tanh + Gaussian log-prob, role-selected
    head2_logprob_kernel<<<M_TOTAL / 8, 256>>>(bufB, role_ids, actions,
                                               hW2, hb2, lsd, out);
}

// round 9
// speedup vs baseline: 1.5417x; 1.5417x over previous
#include <cuda_runtime.h>
#include <cuda_bf16.h>
#include <cstdint>
#include <math.h>

// ---------------------------------------------------------------------------
// ActorMultiHead — tf32 mma.sync GEMMs + role compaction.
//
// Key algebraic cut: tokens with role>=2 output exactly 0 (one_hot select),
// and each surviving token only needs ITS role's head. So:
//   1. compact tokens: role0 -> [0,C0), role1 -> [S1,S1+C1), S1=align128(C0)
//   2. run the 3 shared layers on M2 = align128(C0)+align128(C1) rows (~2/3)
//   3. head1 as two N=512 segment GEMMs (per-role weights)
//   4. head2+logprob scatters back via slot map; role2 -> 0
// GEMM grids are launched at max size and early-exit on device-side [base,lim).
// ---------------------------------------------------------------------------

#define M_TOTAL  32768
#define MMAX     (M_TOTAL + 256)
#define BM 128
#define BN 128
#define BK 32
#define AS_STRIDE 36           // 36 ≡ 4 (mod 32): conflict-free A frag LDS
#define BS_STRIDE 136          // 136 ≡ 8 (mod 32): conflict-free B frag LDS
#define ASZ (BM * AS_STRIDE)
#define BSZ (BK * BS_STRIDE)
#define STG (ASZ + BSZ)
#define SMEM_BYTES (2 * STG * 4)   // 71680 B, 2 stages

#define W0P_OFF 0
#define W1_OFF  (160 * 1024)
#define W2_OFF  (W1_OFF + 1024 * 1024)
#define HW1_OFF (W2_OFF + 1024 * 1024)         // hW1 kept [2][1024][512] order
#define WP_TOTAL (HW1_OFF + 2 * 1024 * 512)

// Scratch (allocation-free __device__ globals)
__device__ float g_bufA[MMAX * 1024];
__device__ float g_bufB[MMAX * 1024];
__device__ float g_xpad[MMAX * 160];
__device__ float g_z[MMAX * 512];
__device__ float g_wp[WP_TOTAL];
__device__ int   g_slot[M_TOTAL];
__device__ int   g_cnt0[256], g_cnt1[256];
__device__ int   g_base0[256], g_base1[256];
__device__ int   g_meta[8];   // 0:0 1:M2 | 2:0 3:S1 | 4:S1 5:M2 | 6:C0 7:C1

__device__ __forceinline__ float tf32_round(float f) {
    unsigned u;
    asm("cvt.rna.tf32.f32 %0, %1;" : "=r"(u) : "f"(f));
    return __uint_as_float(u);
}

__device__ __forceinline__ void mma_tf32(float d[4], const unsigned a[4], const unsigned b[2]) {
    asm("mma.sync.aligned.m16n8k8.row.col.f32.tf32.tf32.f32 "
        "{%0,%1,%2,%3}, {%4,%5,%6,%7}, {%8,%9}, {%0,%1,%2,%3};\n"
        : "+f"(d[0]), "+f"(d[1]), "+f"(d[2]), "+f"(d[3])
        : "r"(a[0]), "r"(a[1]), "r"(a[2]), "r"(a[3]), "r"(b[0]), "r"(b[1]));
}

__device__ __forceinline__ void cp16(unsigned s, const float* g) {
    asm volatile("cp.async.cg.shared.global [%0], [%1], 16;\n" :: "r"(s), "l"(g));
}

// ---------------------------------------------------------------------------
// Compaction: count -> scan -> slot assignment
// ---------------------------------------------------------------------------
__global__ void count_roles(const int* __restrict__ roles)
{
    const int blk = blockIdx.x, tid = threadIdx.x;     // 256 blocks x 128
    const int role = roles[blk * 128 + tid];
    const unsigned m0 = __ballot_sync(0xffffffffu, role == 0);
    const unsigned m1 = __ballot_sync(0xffffffffu, role == 1);
    __shared__ int c0[4], c1[4];
    if ((tid & 31) == 0) { c0[tid >> 5] = __popc(m0); c1[tid >> 5] = __popc(m1); }
    __syncthreads();
    if (tid == 0) {
        g_cnt0[blk] = c0[0] + c0[1] + c0[2] + c0[3];
        g_cnt1[blk] = c1[0] + c1[1] + c1[2] + c1[3];
    }
}

__global__ void scan_roles()
{
    if (threadIdx.x != 0) return;
    int acc = 0;
    for (int i = 0; i < 256; i++) { g_base0[i] = acc; acc += g_cnt0[i]; }
    const int C0 = acc;
    const int S1 = (C0 + 127) & ~127;
    acc = S1;
    for (int i = 0; i < 256; i++) { g_base1[i] = acc; acc += g_cnt1[i]; }
    const int C1 = acc - S1;
    const int M2 = S1 + ((C1 + 127) & ~127);
    g_meta[0] = 0;  g_meta[1] = M2;
    g_meta[2] = 0;  g_meta[3] = S1;
    g_meta[4] = S1; g_meta[5] = M2;
    g_meta[6] = C0; g_meta[7] = C1;
}

__global__ void assign_slots(const int* __restrict__ roles)
{
    const int blk = blockIdx.x, tid = threadIdx.x;     // 256 blocks x 128
    const int t = blk * 128 + tid;
    const int role = roles[t];
    const unsigned lt = (1u << (tid & 31)) - 1u;
    const unsigned m0 = __ballot_sync(0xffffffffu, role == 0);
    const unsigned m1 = __ballot_sync(0xffffffffu, role == 1);
    __shared__ int c0[4], c1[4];
    if ((tid & 31) == 0) { c0[tid >> 5] = __popc(m0); c1[tid >> 5] = __popc(m1); }
    __syncthreads();
    int off0 = 0, off1 = 0;
    for (int w = 0; w < (tid >> 5); w++) { off0 += c0[w]; off1 += c1[w]; }
    int slot = -1;
    if (role == 0)      slot = g_base0[blk] + off0 + __popc(m0 & lt);
    else if (role == 1) slot = g_base1[blk] + off1 + __popc(m1 & lt);
    g_slot[t] = slot;
}

// pack compacted input rows: xp[slot] = tf32(concat(obs, onehot), pad to 160)
__global__ void pack_x_compact(const float* __restrict__ obs,
                               const int* __restrict__ roles,
                               float* __restrict__ xp)
{
    const int t = blockIdx.x;
    const int p = g_slot[t];
    if (p < 0) return;
    const int k = threadIdx.x;          // 0..159
    float v = 0.f;
    if (k < 128)      v = obs[t * 128 + k];
    else if (k < 130) v = (roles[t] == (k - 128)) ? 1.f : 0.f;
    xp[p * 160 + k] = tf32_round(v);
}

// zero the padding rows of xp (deterministic inputs for padded GEMM rows)
__global__ void zero_pads(float* __restrict__ xp)
{
    const int i = blockIdx.x;           // up to 256 pad rows
    const int C0 = g_meta[6], C1 = g_meta[7];
    const int S1 = g_meta[3], M2 = g_meta[1];
    const int p0 = S1 - C0;
    int row;
    if (i < p0) row = C0 + i;
    else if (i - p0 < M2 - (S1 + C1)) row = S1 + C1 + (i - p0);
    else return;
    xp[row * 160 + threadIdx.x] = 0.f;
}

// ---------------------------------------------------------------------------
// Weight prepack (tf32, W0 padded to K=160)
// ---------------------------------------------------------------------------
__global__ void pack_w(const float* __restrict__ W0, const float* __restrict__ W1,
                       const float* __restrict__ W2, const float* __restrict__ hW1,
                       float* __restrict__ wp)
{
    const int idx = blockIdx.x * 256 + threadIdx.x;
    if (idx >= WP_TOTAL) return;
    float v;
    if (idx < W1_OFF) {                        // W0 padded [160,1024]
        int k = idx >> 10, n = idx & 1023;
        v = (k < 130) ? W0[k * 1024 + n] : 0.f;
    } else if (idx < W2_OFF) {
        v = W1[idx - W1_OFF];
    } else if (idx < HW1_OFF) {
        v = W2[idx - W2_OFF];
    } else {
        v = hW1[idx - HW1_OFF];                // [2][1024][512] kept as-is
    }
    wp[idx] = tf32_round(v);
}

// ---------------------------------------------------------------------------
// GEMM: C[rows, N] = relu(A @ B + bias); rows = [mr[0], mr[1]) early-exit.
// 128 threads, 4 warps (2x2), warp tile 64x64, double-buffered cp.async.
// ---------------------------------------------------------------------------
template <int ROUND>
__global__ void __launch_bounds__(128, 2)
gemm_tc(const float* __restrict__ A, int lda,
        const float* __restrict__ B, int ldb,
        const float* __restrict__ bias,
        float* __restrict__ C, int ldc, int K,
        const int* __restrict__ mr)
{
    const int base = mr[0], lim = mr[1];
    const int blockM = base + blockIdx.y * BM;
    if (blockM >= lim) return;
    const int blockN = blockIdx.x * BN;

    extern __shared__ float smem[];
    const int tid  = threadIdx.x;
    const int lane = tid & 31;
    const int warp = tid >> 5;
    const int wm = warp >> 1;
    const int wn = warp & 1;

    const unsigned smemB = (unsigned)__cvta_generic_to_shared(smem);

    const int aRow = tid >> 3, aC = (tid & 7) * 4;
    const int bRow = tid >> 5, bC = (tid & 31) * 4;
    const float* aG0 = A + (size_t)(blockM + aRow) * lda + aC;
    const float* bG0 = B + (size_t)bRow * ldb + blockN + bC;
    const unsigned aS0 = smemB + (unsigned)(aRow * AS_STRIDE + aC) * 4u;
    const unsigned bS0 = smemB + (unsigned)(ASZ + bRow * BS_STRIDE + bC) * 4u;

    auto stage = [&](int kt) {
        const unsigned so = (unsigned)(kt & 1) * (STG * 4u);
        const float* ag = aG0 + kt * BK;
        const float* bg = bG0 + (size_t)kt * BK * ldb;
#pragma unroll
        for (int i = 0; i < 8; i++)
            cp16(aS0 + so + (unsigned)(i * 16 * AS_STRIDE * 4), ag + (size_t)i * 16 * lda);
#pragma unroll
        for (int i = 0; i < 8; i++)
            cp16(bS0 + so + (unsigned)(i * 4 * BS_STRIDE * 4), bg + (size_t)i * 4 * ldb);
        asm volatile("cp.async.commit_group;\n");
    };

    float acc[4][8][4];
#pragma unroll
    for (int mi = 0; mi < 4; mi++)
#pragma unroll
        for (int ni = 0; ni < 8; ni++)
#pragma unroll
            for (int c = 0; c < 4; c++) acc[mi][ni][c] = 0.f;

    const int T = K >> 5;
    stage(0);

    for (int kt = 0; kt < T; kt++) {
        if (kt + 1 < T) {
            stage(kt + 1);
            asm volatile("cp.async.wait_group 1;\n" ::: "memory");
        } else {
            asm volatile("cp.async.wait_group 0;\n" ::: "memory");
        }
        __syncthreads();

        const float* as = smem + (kt & 1) * STG;
        const float* bs = as + ASZ;

#pragma unroll
        for (int ks = 0; ks < BK / 8; ks++) {
            unsigned a[4][4], b[8][2];
            const int ac = ks * 8 + (lane & 3);
#pragma unroll
            for (int mi = 0; mi < 4; mi++) {
                const int ar = wm * 64 + mi * 16 + (lane >> 2);
                a[mi][0] = __float_as_uint(as[ar * AS_STRIDE + ac]);
                a[mi][1] = __float_as_uint(as[(ar + 8) * AS_STRIDE + ac]);
                a[mi][2] = __float_as_uint(as[ar * AS_STRIDE + ac + 4]);
                a[mi][3] = __float_as_uint(as[(ar + 8) * AS_STRIDE + ac + 4]);
            }
            const int br  = ks * 8 + (lane & 3);
            const int bc0 = wn * 64 + (lane >> 2);
#pragma unroll
            for (int ni = 0; ni < 8; ni++) {
                b[ni][0] = __float_as_uint(bs[br * BS_STRIDE + bc0 + ni * 8]);
                b[ni][1] = __float_as_uint(bs[(br + 4) * BS_STRIDE + bc0 + ni * 8]);
            }
#pragma unroll
            for (int mi = 0; mi < 4; mi++)
#pragma unroll
                for (int ni = 0; ni < 8; ni++)
                    mma_tf32(acc[mi][ni], a[mi], b[ni]);
        }
        __syncthreads();
    }

#pragma unroll
    for (int ni = 0; ni < 8; ni++) {
        const int col = blockN + wn * 64 + ni * 8 + 2 * (lane & 3);
        const float bb0 = bias[col];
        const float bb1 = bias[col + 1];
#pragma unroll
        for (int mi = 0; mi < 4; mi++) {
            const int row = blockM + wm * 64 + mi * 16 + (lane >> 2);
            float v0 = fmaxf(acc[mi][ni][0] + bb0, 0.f);
            float v1 = fmaxf(acc[mi][ni][1] + bb1, 0.f);
            float v2 = fmaxf(acc[mi][ni][2] + bb0, 0.f);
            float v3 = fmaxf(acc[mi][ni][3] + bb1, 0.f);
            if (ROUND) {
                v0 = tf32_round(v0); v1 = tf32_round(v1);
                v2 = tf32_round(v2); v3 = tf32_round(v3);
            }
            *(float2*)&C[(size_t)row * ldc + col]       = make_float2(v0, v1);
            *(float2*)&C[(size_t)(row + 8) * ldc + col] = make_float2(v2, v3);
        }
    }
}

// ---------------------------------------------------------------------------
// Head layer 2 + tanh + Gaussian log prob; gathers via slot map.
// ---------------------------------------------------------------------------
__global__ void __launch_bounds__(256)
head2_logprob_kernel(const float* __restrict__ Z,        // [M2,512] compact
                     const int*   __restrict__ role_ids,
                     const float* __restrict__ actions,
                     const float* __restrict__ hW2,      // [2*512*8]
                     const float* __restrict__ hb2,
                     const float* __restrict__ logstd,
                     float* __restrict__ out)
{
    __shared__ float sW[2 * 8 * 512];  // [r][k][m]
    __shared__ float sb[16];
    __shared__ float sls[16];

    const int tid = threadIdx.x;
    for (int idx = tid; idx < 8192; idx += 256) {
        int r = idx >> 12, rem = idx & 4095, m = rem >> 3, k = rem & 7;
        sW[r * 4096 + k * 512 + m] = hW2[idx];
    }
    if (tid < 16) { sb[tid] = hb2[tid]; sls[tid] = logstd[tid]; }
    __syncthreads();

    const int warp = tid >> 5, lane = tid & 31;
    const int t = blockIdx.x * 8 + warp;

    const int role = role_ids[t];
    if (role >= 2) { if (lane == 0) out[t] = 0.f; return; }
    const int p = g_slot[t];

    const float* z = Z + (size_t)p * 512;
    const float* w = sW + role * 4096;

    float s[8];
#pragma unroll
    for (int k = 0; k < 8; k++) s[k] = 0.f;
#pragma unroll
    for (int j = 0; j < 16; j++) {
        int m = lane + j * 32;
        float zv = z[m];
#pragma unroll
        for (int k = 0; k < 8; k++) s[k] += zv * w[k * 512 + m];
    }
#pragma unroll
    for (int k = 0; k < 8; k++)
#pragma unroll
        for (int off = 16; off; off >>= 1)
            s[k] += __shfl_xor_sync(0xffffffffu, s[k], off);

    if (lane == 0) {
        float lp = 0.f;
#pragma unroll
        for (int k = 0; k < 8; k++) {
            float mean = tanhf(s[k] + sb[role * 8 + k]);
            float ls = sls[role * 8 + k];
            float d = (actions[t * 8 + k] - mean) * expf(-ls);
            lp += -0.5f * d * d - ls - 0.91893853320467274178f;
        }
        out[t] = lp;
    }
}

extern "C" void kernel_launch(void* const* d_in, const int* in_sizes, int n_in,
                              void* d_out, int out_size)
{
    const float* obs      = (const float*)d_in[0];
    const int*   role_ids = (const int*)  d_in[1];
    const float* actions  = (const float*)d_in[2];
    const float* W0  = (const float*)d_in[3];
    const float* b0  = (const float*)d_in[4];
    const float* W1  = (const float*)d_in[5];
    const float* b1  = (const float*)d_in[6];
    const float* W2  = (const float*)d_in[7];
    const float* b2  = (const float*)d_in[8];
    const float* hW1 = (const float*)d_in[9];
    const float* hb1 = (const float*)d_in[10];  // [2,512]
    const float* hW2 = (const float*)d_in[11];
    const float* hb2 = (const float*)d_in[12];
    const float* lsd = (const float*)d_in[13];
    float* out = (float*)d_out;

    float *bufA, *bufB, *xpad, *zb, *wp;
    int *meta;
    cudaGetSymbolAddress((void**)&bufA, g_bufA);
    cudaGetSymbolAddress((void**)&bufB, g_bufB);
    cudaGetSymbolAddress((void**)&xpad, g_xpad);
    cudaGetSymbolAddress((void**)&zb,   g_z);
    cudaGetSymbolAddress((void**)&wp,   g_wp);
    cudaGetSymbolAddress((void**)&meta, g_meta);

    cudaFuncSetAttribute(gemm_tc<1>, cudaFuncAttributeMaxDynamicSharedMemorySize, SMEM_BYTES);
    cudaFuncSetAttribute(gemm_tc<0>, cudaFuncAttributeMaxDynamicSharedMemorySize, SMEM_BYTES);

    // compaction + prepack
    count_roles<<<256, 128>>>(role_ids);
    scan_roles<<<1, 32>>>();
    assign_slots<<<256, 128>>>(role_ids);
    pack_x_compact<<<M_TOTAL, 160>>>(obs, role_ids, xpad);
    zero_pads<<<256, 160>>>(xpad);
    pack_w<<<(WP_TOTAL + 255) / 256, 256>>>(W0, W1, W2, hW1, wp);

    const int GY = MMAX / BM;             // 258, blocks early-exit past limit
    dim3 block(128);
    dim3 gridMain(8, GY);                 // N=1024
    dim3 gridHead(4, GY);                 // N=512

    // shared layers on compacted rows [0, M2)
    gemm_tc<1><<<gridMain, block, SMEM_BYTES>>>(xpad, 160,  wp + W0P_OFF, 1024, b0, bufA, 1024, 160,  meta + 0);
    gemm_tc<1><<<gridMain, block, SMEM_BYTES>>>(bufA, 1024, wp + W1_OFF,  1024, b1, bufB, 1024, 1024, meta + 0);
    gemm_tc<1><<<gridMain, block, SMEM_BYTES>>>(bufB, 1024, wp + W2_OFF,  1024, b2, bufA, 1024, 1024, meta + 0);
    // role-split head1: rows [0,S1) x hW1[0], rows [S1,M2) x hW1[1]
    gemm_tc<0><<<gridHead, block, SMEM_BYTES>>>(bufA, 1024, wp + HW1_OFF,            512, hb1,       zb, 512, 1024, meta + 2);
    gemm_tc<0><<<gridHead, block, SMEM_BYTES>>>(bufA, 1024, wp + HW1_OFF + 1024*512, 512, hb1 + 512, zb, 512, 1024, meta + 4);
    // head2 + tanh + Gaussian log-prob, scatter via slot map
    head2_logprob_kernel<<<M_TOTAL / 8, 256>>>(zb, role_ids, actions,
                                               hW2, hb2, lsd, out);
}

// round 10
// speedup vs baseline: 1.5780x; 1.0235x over previous
#include <cuda_runtime.h>
#include <cuda_fp16.h>
#include <cstdint>
#include <math.h>

// ---------------------------------------------------------------------------
// ActorMultiHead — fp16 mma.sync (m16n8k16, fp32 accum) + role compaction.
//
// fp16 mantissa (10 bits) == tf32 mantissa, so precision matches the prior
// tf32 build while the HMMA rate and memory traffic double/halve.
//   1. compact tokens: role0 -> [0,C0), role1 -> [S1,S1+C1), S1=align128(C0)
//   2. 3 shared layers on M2 rows (~2/3 of tokens), fp16 in / fp32 acc
//   3. head1 as two N=512 segment GEMMs (per-role weights)
//   4. head2+logprob gathers via slot map; role2 -> exact 0
// Weights pre-packed fp16 TRANSPOSED [N][K]; activations fp16 [M][K].
// ---------------------------------------------------------------------------

#define M_TOTAL  32768
#define MMAX     (M_TOTAL + 256)
#define BM 128
#define BN 128
#define BK 32
#define TS 40                        // smem row stride in halfs (80B): conflict-free
#define TILE_H (128 * TS)            // 5120 halfs per (A|B) tile
#define STG_H  (2 * TILE_H)          // 10240 halfs per stage
// static smem: 2 stages * 20480B = 40960B

// fp16 transposed weight pack offsets (halfs)
#define W0T_OFF  0                               // [1024][160]
#define W1T_OFF  (1024 * 160)
#define W2T_OFF  (W1T_OFF + 1024 * 1024)
#define HW1T_OFF (W2T_OFF + 1024 * 1024)         // [2][512][1024]
#define WT_TOTAL (HW1T_OFF + 2 * 512 * 1024)

// Scratch (allocation-free __device__ globals)
__device__ __half g_bufA[MMAX * 1024];
__device__ __half g_bufB[MMAX * 1024];
__device__ __half g_xpad[MMAX * 160];
__device__ __half g_z[MMAX * 512];
__device__ __half g_wt[WT_TOTAL];
__device__ int   g_slot[M_TOTAL];
__device__ int   g_cnt0[256], g_cnt1[256];
__device__ int   g_base0[256], g_base1[256];
__device__ int   g_meta[8];   // 0:0 1:M2 | 2:0 3:S1 | 4:S1 5:M2 | 6:C0 7:C1

__device__ __forceinline__ void mma_f16(float d[4], const unsigned a[4], const unsigned b[2]) {
    asm("mma.sync.aligned.m16n8k16.row.col.f32.f16.f16.f32 "
        "{%0,%1,%2,%3}, {%4,%5,%6,%7}, {%8,%9}, {%0,%1,%2,%3};\n"
        : "+f"(d[0]), "+f"(d[1]), "+f"(d[2]), "+f"(d[3])
        : "r"(a[0]), "r"(a[1]), "r"(a[2]), "r"(a[3]), "r"(b[0]), "r"(b[1]));
}

__device__ __forceinline__ void cp16(unsigned s, const void* g) {
    asm volatile("cp.async.cg.shared.global [%0], [%1], 16;\n" :: "r"(s), "l"(g));
}

// ---------------------------------------------------------------------------
// Compaction: count -> scan -> slot assignment
// ---------------------------------------------------------------------------
__global__ void count_roles(const int* __restrict__ roles)
{
    const int blk = blockIdx.x, tid = threadIdx.x;     // 256 x 128
    const int role = roles[blk * 128 + tid];
    const unsigned m0 = __ballot_sync(0xffffffffu, role == 0);
    const unsigned m1 = __ballot_sync(0xffffffffu, role == 1);
    __shared__ int c0[4], c1[4];
    if ((tid & 31) == 0) { c0[tid >> 5] = __popc(m0); c1[tid >> 5] = __popc(m1); }
    __syncthreads();
    if (tid == 0) {
        g_cnt0[blk] = c0[0] + c0[1] + c0[2] + c0[3];
        g_cnt1[blk] = c1[0] + c1[1] + c1[2] + c1[3];
    }
}

__global__ void scan_roles()
{
    if (threadIdx.x != 0) return;
    int acc = 0;
    for (int i = 0; i < 256; i++) { g_base0[i] = acc; acc += g_cnt0[i]; }
    const int C0 = acc;
    const int S1 = (C0 + 127) & ~127;
    acc = S1;
    for (int i = 0; i < 256; i++) { g_base1[i] = acc; acc += g_cnt1[i]; }
    const int C1 = acc - S1;
    const int M2 = S1 + ((C1 + 127) & ~127);
    g_meta[0] = 0;  g_meta[1] = M2;
    g_meta[2] = 0;  g_meta[3] = S1;
    g_meta[4] = S1; g_meta[5] = M2;
    g_meta[6] = C0; g_meta[7] = C1;
}

__global__ void assign_slots(const int* __restrict__ roles)
{
    const int blk = blockIdx.x, tid = threadIdx.x;
    const int t = blk * 128 + tid;
    const int role = roles[t];
    const unsigned lt = (1u << (tid & 31)) - 1u;
    const unsigned m0 = __ballot_sync(0xffffffffu, role == 0);
    const unsigned m1 = __ballot_sync(0xffffffffu, role == 1);
    __shared__ int c0[4], c1[4];
    if ((tid & 31) == 0) { c0[tid >> 5] = __popc(m0); c1[tid >> 5] = __popc(m1); }
    __syncthreads();
    int off0 = 0, off1 = 0;
    for (int w = 0; w < (tid >> 5); w++) { off0 += c0[w]; off1 += c1[w]; }
    int slot = -1;
    if (role == 0)      slot = g_base0[blk] + off0 + __popc(m0 & lt);
    else if (role == 1) slot = g_base1[blk] + off1 + __popc(m1 & lt);
    g_slot[t] = slot;
}

// xp[slot] = fp16(concat(obs, onehot), zero-pad to 160)
__global__ void pack_x_compact(const float* __restrict__ obs,
                               const int* __restrict__ roles,
                               __half* __restrict__ xp)
{
    const int t = blockIdx.x;
    const int p = g_slot[t];
    if (p < 0) return;
    const int k = threadIdx.x;          // 0..159
    float v = 0.f;
    if (k < 128)      v = obs[t * 128 + k];
    else if (k < 130) v = (roles[t] == (k - 128)) ? 1.f : 0.f;
    xp[p * 160 + k] = __float2half(v);
}

__global__ void zero_pads(__half* __restrict__ xp)
{
    const int i = blockIdx.x;           // up to 256 pad rows
    const int C0 = g_meta[6], C1 = g_meta[7];
    const int S1 = g_meta[3], M2 = g_meta[1];
    const int p0 = S1 - C0;
    int row;
    if (i < p0) row = C0 + i;
    else if (i - p0 < M2 - (S1 + C1)) row = S1 + C1 + (i - p0);
    else return;
    xp[row * 160 + threadIdx.x] = __float2half(0.f);
}

// ---------------------------------------------------------------------------
// Weight transpose-pack: dst[n][k] = fp16(src[k][n]), k >= srcK -> 0
// grid (dstLdK/32, N/32), block (32,8)
// ---------------------------------------------------------------------------
__global__ void transposeH(const float* __restrict__ src, int srcK, int srcN,
                           __half* __restrict__ dst, int dstLdK)
{
    __shared__ float tile[32][33];
    const int k0 = blockIdx.x * 32, n0 = blockIdx.y * 32;
    for (int i = threadIdx.y; i < 32; i += 8) {
        int k = k0 + i;
        tile[i][threadIdx.x] = (k < srcK) ? src[(size_t)k * srcN + n0 + threadIdx.x] : 0.f;
    }
    __syncthreads();
    for (int i = threadIdx.y; i < 32; i += 8)
        dst[(size_t)(n0 + i) * dstLdK + k0 + threadIdx.x] =
            __float2half(tile[threadIdx.x][i]);
}

// ---------------------------------------------------------------------------
// fp16 GEMM: C[rows,N] = fp16(relu(A @ Bt^T + bias)); rows=[mr[0],mr[1]).
// A [M][K] fp16 row-major, Bt [N][K] fp16 row-major (i.e. B transposed).
// 128 threads, 4 warps (2x2), warp tile 64x64, double-buffered cp.async.
// ---------------------------------------------------------------------------
__global__ void __launch_bounds__(128, 2)
gemm_f16(const __half* __restrict__ A, int lda,
         const __half* __restrict__ Bt, int ldb,
         const float* __restrict__ bias,
         __half* __restrict__ C, int ldc, int K,
         const int* __restrict__ mr)
{
    const int base = mr[0], lim = mr[1];
    const int blockM = base + blockIdx.y * BM;
    if (blockM >= lim) return;
    const int blockN = blockIdx.x * BN;

    __shared__ __half smem[2 * STG_H];   // 40960 B
    const unsigned smemB = (unsigned)__cvta_generic_to_shared(smem);

    const int tid  = threadIdx.x;
    const int lane = tid & 31;
    const int warp = tid >> 5;
    const int wm = warp >> 1;
    const int wn = warp & 1;

    // staging: thread t copies row t of A tile and row t of B tile (32 halfs each)
    const __half* aG0 = A  + (size_t)(blockM + tid) * lda;
    const __half* bG0 = Bt + (size_t)(blockN + tid) * ldb;
    const unsigned aS0 = smemB + (unsigned)tid * (TS * 2);
    const unsigned bS0 = smemB + (unsigned)(TILE_H * 2) + (unsigned)tid * (TS * 2);

    auto stage = [&](int kt) {
        const unsigned so = (unsigned)(kt & 1) * (STG_H * 2);
        const __half* ag = aG0 + kt * BK;
        const __half* bg = bG0 + kt * BK;
#pragma unroll
        for (int i = 0; i < 4; i++) cp16(aS0 + so + i * 16, ag + i * 8);
#pragma unroll
        for (int i = 0; i < 4; i++) cp16(bS0 + so + i * 16, bg + i * 8);
        asm volatile("cp.async.commit_group;\n");
    };

    float acc[4][8][4];
#pragma unroll
    for (int mi = 0; mi < 4; mi++)
#pragma unroll
        for (int ni = 0; ni < 8; ni++)
#pragma unroll
            for (int c = 0; c < 4; c++) acc[mi][ni][c] = 0.f;

    const int T = K >> 5;
    stage(0);

    for (int kt = 0; kt < T; kt++) {
        if (kt + 1 < T) {
            stage(kt + 1);
            asm volatile("cp.async.wait_group 1;\n" ::: "memory");
        } else {
            asm volatile("cp.async.wait_group 0;\n" ::: "memory");
        }
        __syncthreads();

        const __half* as = smem + (kt & 1) * STG_H;
        const __half* bs = as + TILE_H;

#pragma unroll
        for (int ks = 0; ks < 2; ks++) {               // two k16 steps per BK=32
            const int kb = ks * 16 + 2 * (lane & 3);
            unsigned a[4][4], b[8][2];
#pragma unroll
            for (int mi = 0; mi < 4; mi++) {
                const int ar = wm * 64 + mi * 16 + (lane >> 2);
                a[mi][0] = *(const unsigned*)(as + ar * TS + kb);
                a[mi][1] = *(const unsigned*)(as + (ar + 8) * TS + kb);
                a[mi][2] = *(const unsigned*)(as + ar * TS + kb + 8);
                a[mi][3] = *(const unsigned*)(as + (ar + 8) * TS + kb + 8);
            }
#pragma unroll
            for (int ni = 0; ni < 8; ni++) {
                const int bn = wn * 64 + ni * 8 + (lane >> 2);
                b[ni][0] = *(const unsigned*)(bs + bn * TS + kb);
                b[ni][1] = *(const unsigned*)(bs + bn * TS + kb + 8);
            }
#pragma unroll
            for (int mi = 0; mi < 4; mi++)
#pragma unroll
                for (int ni = 0; ni < 8; ni++)
                    mma_f16(acc[mi][ni], a[mi], b[ni]);
        }
        __syncthreads();
    }

    // epilogue: bias + relu -> fp16 store (half2)
#pragma unroll
    for (int ni = 0; ni < 8; ni++) {
        const int col = blockN + wn * 64 + ni * 8 + 2 * (lane & 3);
        const float bb0 = bias[col];
        const float bb1 = bias[col + 1];
#pragma unroll
        for (int mi = 0; mi < 4; mi++) {
            const int row = blockM + wm * 64 + mi * 16 + (lane >> 2);
            float v0 = fmaxf(acc[mi][ni][0] + bb0, 0.f);
            float v1 = fmaxf(acc[mi][ni][1] + bb1, 0.f);
            float v2 = fmaxf(acc[mi][ni][2] + bb0, 0.f);
            float v3 = fmaxf(acc[mi][ni][3] + bb1, 0.f);
            *(__half2*)&C[(size_t)row * ldc + col]       = __floats2half2_rn(v0, v1);
            *(__half2*)&C[(size_t)(row + 8) * ldc + col] = __floats2half2_rn(v2, v3);
        }
    }
}

// ---------------------------------------------------------------------------
// Head layer 2 + tanh + Gaussian log prob; gathers fp16 Z via slot map.
// ---------------------------------------------------------------------------
__global__ void __launch_bounds__(256)
head2_logprob_kernel(const __half* __restrict__ Z,      // [M2,512] compact fp16
                     const int*   __restrict__ role_ids,
                     const float* __restrict__ actions,
                     const float* __restrict__ hW2,     // [2*512*8]
                     const float* __restrict__ hb2,
                     const float* __restrict__ logstd,
                     float* __restrict__ out)
{
    __shared__ float sW[2 * 8 * 512];  // [r][k][m]
    __shared__ float sb[16];
    __shared__ float sls[16];

    const int tid = threadIdx.x;
    for (int idx = tid; idx < 8192; idx += 256) {
        int r = idx >> 12, rem = idx & 4095, m = rem >> 3, k = rem & 7;
        sW[r * 4096 + k * 512 + m] = hW2[idx];
    }
    if (tid < 16) { sb[tid] = hb2[tid]; sls[tid] = logstd[tid]; }
    __syncthreads();

    const int warp = tid >> 5, lane = tid & 31;
    const int t = blockIdx.x * 8 + warp;

    const int role = role_ids[t];
    if (role >= 2) { if (lane == 0) out[t] = 0.f; return; }
    const int p = g_slot[t];

    const __half2* z2 = (const __half2*)(Z + (size_t)p * 512);
    const float* w = sW + role * 4096;

    float s[8];
#pragma unroll
    for (int k = 0; k < 8; k++) s[k] = 0.f;
#pragma unroll
    for (int j = 0; j < 8; j++) {
        const int i2 = lane + j * 32;            // half2 index, 256 total
        const float2 zf = __half22float2(z2[i2]);
        const int m = i2 * 2;
#pragma unroll
        for (int k = 0; k < 8; k++)
            s[k] += zf.x * w[k * 512 + m] + zf.y * w[k * 512 + m + 1];
    }
#pragma unroll
    for (int k = 0; k < 8; k++)
#pragma unroll
        for (int off = 16; off; off >>= 1)
            s[k] += __shfl_xor_sync(0xffffffffu, s[k], off);

    if (lane == 0) {
        float lp = 0.f;
#pragma unroll
        for (int k = 0; k < 8; k++) {
            float mean = tanhf(s[k] + sb[role * 8 + k]);
            float ls = sls[role * 8 + k];
            float d = (actions[t * 8 + k] - mean) * expf(-ls);
            lp += -0.5f * d * d - ls - 0.91893853320467274178f;
        }
        out[t] = lp;
    }
}

extern "C" void kernel_launch(void* const* d_in, const int* in_sizes, int n_in,
                              void* d_out, int out_size)
{
    const float* obs      = (const float*)d_in[0];
    const int*   role_ids = (const int*)  d_in[1];
    const float* actions  = (const float*)d_in[2];
    const float* W0  = (const float*)d_in[3];
    const float* b0  = (const float*)d_in[4];
    const float* W1  = (const float*)d_in[5];
    const float* b1  = (const float*)d_in[6];
    const float* W2  = (const float*)d_in[7];
    const float* b2  = (const float*)d_in[8];
    const float* hW1 = (const float*)d_in[9];
    const float* hb1 = (const float*)d_in[10];  // [2,512]
    const float* hW2 = (const float*)d_in[11];
    const float* hb2 = (const float*)d_in[12];
    const float* lsd = (const float*)d_in[13];
    float* out = (float*)d_out;

    __half *bufA, *bufB, *xpad, *zb, *wt;
    int *meta;
    cudaGetSymbolAddress((void**)&bufA, g_bufA);
    cudaGetSymbolAddress((void**)&bufB, g_bufB);
    cudaGetSymbolAddress((void**)&xpad, g_xpad);
    cudaGetSymbolAddress((void**)&zb,   g_z);
    cudaGetSymbolAddress((void**)&wt,   g_wt);
    cudaGetSymbolAddress((void**)&meta, g_meta);

    // compaction + packs
    count_roles<<<256, 128>>>(role_ids);
    scan_roles<<<1, 32>>>();
    assign_slots<<<256, 128>>>(role_ids);
    pack_x_compact<<<M_TOTAL, 160>>>(obs, role_ids, xpad);
    zero_pads<<<256, 160>>>(xpad);

    dim3 tb(32, 8);
    transposeH<<<dim3(5, 32),  tb>>>(W0,  130,  1024, wt + W0T_OFF,  160);
    transposeH<<<dim3(32, 32), tb>>>(W1,  1024, 1024, wt + W1T_OFF,  1024);
    transposeH<<<dim3(32, 32), tb>>>(W2,  1024, 1024, wt + W2T_OFF,  1024);
    transposeH<<<dim3(32, 16), tb>>>(hW1,             1024, 512, wt + HW1T_OFF,             1024);
    transposeH<<<dim3(32, 16), tb>>>(hW1 + 1024*512,  1024, 512, wt + HW1T_OFF + 512*1024,  1024);

    const int GY = MMAX / BM;             // 258, blocks early-exit past limit
    dim3 block(128);
    dim3 gridMain(8, GY);                 // N=1024
    dim3 gridHead(4, GY);                 // N=512

    // shared layers on compacted rows [0, M2)
    gemm_f16<<<gridMain, block>>>(xpad, 160,  wt + W0T_OFF, 160,  b0, bufA, 1024, 160,  meta + 0);
    gemm_f16<<<gridMain, block>>>(bufA, 1024, wt + W1T_OFF, 1024, b1, bufB, 1024, 1024, meta + 0);
    gemm_f16<<<gridMain, block>>>(bufB, 1024, wt + W2T_OFF, 1024, b2, bufA, 1024, 1024, meta + 0);
    // role-split head1: rows [0,S1) x hW1[0], rows [S1,M2) x hW1[1]
    gemm_f16<<<gridHead, block>>>(bufA, 1024, wt + HW1T_OFF,            1024, hb1,       zb, 512, 1024, meta + 2);
    gemm_f16<<<gridHead, block>>>(bufA, 1024, wt + HW1T_OFF + 512*1024, 1024, hb1 + 512, zb, 512, 1024, meta + 4);
    // head2 + tanh + Gaussian log-prob, gather via slot map
    head2_logprob_kernel<<<M_TOTAL / 8, 256>>>(zb, role_ids, actions,
                                               hW2, hb2, lsd, out);
}

// round 11
// speedup vs baseline: 2.0034x; 1.2696x over previous
#include <cuda_runtime.h>
#include <cuda_fp16.h>
#include <cstdint>
#include <math.h>

// ---------------------------------------------------------------------------
// ActorMultiHead — fp16 mma.sync (m16n8k16, fp32 accum) + role compaction.
// R11: 256-thread GEMM CTAs (4 warps/SMSP for latency hiding), fused head1.
//
//   1. compact tokens: role0 -> [0,C0), role1 -> [S1,S1+C1), S1=align128(C0)
//   2. 3 shared layers on M2 rows (~2/3 of tokens), fp16 in / fp32 acc
//   3. head1 ONE launch over [0,M2); per-block weight select at S1 boundary
//   4. head2+logprob gathers via slot map; role2 -> exact 0
// Weights pre-packed fp16 TRANSPOSED [N][K]; activations fp16 [M][K].
// ---------------------------------------------------------------------------

#define M_TOTAL  32768
#define MMAX     (M_TOTAL + 256)
#define BM 128
#define BN 128
#define BK 32
#define TS 40                        // smem row stride in halfs (80B): conflict-free
#define TILE_H (128 * TS)            // 5120 halfs per (A|B) tile
#define STG_H  (2 * TILE_H)          // 10240 halfs per stage; 2 stages = 40960B

// fp16 transposed weight pack offsets (halfs)
#define W0T_OFF  0                               // [1024][160]
#define W1T_OFF  (1024 * 160)
#define W2T_OFF  (W1T_OFF + 1024 * 1024)
#define HW1T_OFF (W2T_OFF + 1024 * 1024)         // [2][512][1024]
#define WT_TOTAL (HW1T_OFF + 2 * 512 * 1024)

// Scratch (allocation-free __device__ globals)
__device__ __half g_bufA[MMAX * 1024];
__device__ __half g_bufB[MMAX * 1024];
__device__ __half g_xpad[MMAX * 160];
__device__ __half g_z[MMAX * 512];
__device__ __half g_wt[WT_TOTAL];
__device__ int   g_slot[M_TOTAL];
__device__ int   g_cnt0[256], g_cnt1[256];
__device__ int   g_base0[256], g_base1[256];
__device__ int   g_meta[8];   // 1:M2  3:S1  6:C0  7:C1

__device__ __forceinline__ void mma_f16(float d[4], const unsigned a[4], const unsigned b[2]) {
    asm("mma.sync.aligned.m16n8k16.row.col.f32.f16.f16.f32 "
        "{%0,%1,%2,%3}, {%4,%5,%6,%7}, {%8,%9}, {%0,%1,%2,%3};\n"
        : "+f"(d[0]), "+f"(d[1]), "+f"(d[2]), "+f"(d[3])
        : "r"(a[0]), "r"(a[1]), "r"(a[2]), "r"(a[3]), "r"(b[0]), "r"(b[1]));
}

__device__ __forceinline__ void cp16(unsigned s, const void* g) {
    asm volatile("cp.async.cg.shared.global [%0], [%1], 16;\n" :: "r"(s), "l"(g));
}

// ---------------------------------------------------------------------------
// Compaction: count -> scan -> slot assignment
// ---------------------------------------------------------------------------
__global__ void count_roles(const int* __restrict__ roles)
{
    const int blk = blockIdx.x, tid = threadIdx.x;     // 256 x 128
    const int role = roles[blk * 128 + tid];
    const unsigned m0 = __ballot_sync(0xffffffffu, role == 0);
    const unsigned m1 = __ballot_sync(0xffffffffu, role == 1);
    __shared__ int c0[4], c1[4];
    if ((tid & 31) == 0) { c0[tid >> 5] = __popc(m0); c1[tid >> 5] = __popc(m1); }
    __syncthreads();
    if (tid == 0) {
        g_cnt0[blk] = c0[0] + c0[1] + c0[2] + c0[3];
        g_cnt1[blk] = c1[0] + c1[1] + c1[2] + c1[3];
    }
}

__global__ void scan_roles()
{
    if (threadIdx.x != 0) return;
    int acc = 0;
    for (int i = 0; i < 256; i++) { g_base0[i] = acc; acc += g_cnt0[i]; }
    const int C0 = acc;
    const int S1 = (C0 + 127) & ~127;
    acc = S1;
    for (int i = 0; i < 256; i++) { g_base1[i] = acc; acc += g_cnt1[i]; }
    const int C1 = acc - S1;
    const int M2 = S1 + ((C1 + 127) & ~127);
    g_meta[0] = 0;  g_meta[1] = M2;
    g_meta[2] = 0;  g_meta[3] = S1;
    g_meta[4] = S1; g_meta[5] = M2;
    g_meta[6] = C0; g_meta[7] = C1;
}

__global__ void assign_slots(const int* __restrict__ roles)
{
    const int blk = blockIdx.x, tid = threadIdx.x;
    const int t = blk * 128 + tid;
    const int role = roles[t];
    const unsigned lt = (1u << (tid & 31)) - 1u;
    const unsigned m0 = __ballot_sync(0xffffffffu, role == 0);
    const unsigned m1 = __ballot_sync(0xffffffffu, role == 1);
    __shared__ int c0[4], c1[4];
    if ((tid & 31) == 0) { c0[tid >> 5] = __popc(m0); c1[tid >> 5] = __popc(m1); }
    __syncthreads();
    int off0 = 0, off1 = 0;
    for (int w = 0; w < (tid >> 5); w++) { off0 += c0[w]; off1 += c1[w]; }
    int slot = -1;
    if (role == 0)      slot = g_base0[blk] + off0 + __popc(m0 & lt);
    else if (role == 1) slot = g_base1[blk] + off1 + __popc(m1 & lt);
    g_slot[t] = slot;
}

// xp[slot] = fp16(concat(obs, onehot), zero-pad to 160); 8 tokens per block
__global__ void pack_x_compact(const float* __restrict__ obs,
                               const int* __restrict__ roles,
                               __half* __restrict__ xp)
{
    const int k = threadIdx.x;          // 0..159
#pragma unroll
    for (int j = 0; j < 8; j++) {
        const int t = blockIdx.x * 8 + j;
        const int p = g_slot[t];
        if (p < 0) continue;
        float v = 0.f;
        if (k < 128)      v = obs[t * 128 + k];
        else if (k < 130) v = (roles[t] == (k - 128)) ? 1.f : 0.f;
        xp[p * 160 + k] = __float2half(v);
    }
}

__global__ void zero_pads(__half* __restrict__ xp)
{
    const int i = blockIdx.x;           // up to 256 pad rows
    const int C0 = g_meta[6], C1 = g_meta[7];
    const int S1 = g_meta[3], M2 = g_meta[1];
    const int p0 = S1 - C0;
    int row;
    if (i < p0) row = C0 + i;
    else if (i - p0 < M2 - (S1 + C1)) row = S1 + C1 + (i - p0);
    else return;
    xp[row * 160 + threadIdx.x] = __float2half(0.f);
}

// ---------------------------------------------------------------------------
// Weight transpose-pack: dst[n][k] = fp16(src[k][n]), k >= srcK -> 0
// ---------------------------------------------------------------------------
__global__ void transposeH(const float* __restrict__ src, int srcK, int srcN,
                           __half* __restrict__ dst, int dstLdK)
{
    __shared__ float tile[32][33];
    const int k0 = blockIdx.x * 32, n0 = blockIdx.y * 32;
    for (int i = threadIdx.y; i < 32; i += 8) {
        int k = k0 + i;
        tile[i][threadIdx.x] = (k < srcK) ? src[(size_t)k * srcN + n0 + threadIdx.x] : 0.f;
    }
    __syncthreads();
    for (int i = threadIdx.y; i < 32; i += 8)
        dst[(size_t)(n0 + i) * dstLdK + k0 + threadIdx.x] =
            __float2half(tile[threadIdx.x][i]);
}

// ---------------------------------------------------------------------------
// fp16 GEMM: C[rows,N] = fp16(relu(A @ Bt^T + bias)); rows=[0, meta[1]).
// SPLIT=1: blocks with blockM >= meta[3] use (Bt1, bias1).
// 256 threads, 8 warps (4x2), warp tile 32x64, double-buffered cp.async.
// ---------------------------------------------------------------------------
template <int SPLIT>
__global__ void __launch_bounds__(256, 2)
gemm_f16(const __half* __restrict__ A, int lda,
         const __half* __restrict__ Bt0, const __half* __restrict__ Bt1, int ldb,
         const float* __restrict__ bias0, const float* __restrict__ bias1,
         __half* __restrict__ C, int ldc, int K,
         const int* __restrict__ meta)
{
    const int blockM = blockIdx.y * BM;
    if (blockM >= meta[1]) return;
    const int blockN = blockIdx.x * BN;

    const __half* Bt = Bt0;
    const float* bias = bias0;
    if (SPLIT && blockM >= meta[3]) { Bt = Bt1; bias = bias1; }

    __shared__ __half smem[2 * STG_H];   // 40960 B
    const unsigned smemB = (unsigned)__cvta_generic_to_shared(smem);

    const int tid  = threadIdx.x;
    const int lane = tid & 31;
    const int warp = tid >> 5;
    const int wm = warp >> 1;            // 4 warps along M (32 rows each)
    const int wn = warp & 1;             // 2 warps along N (64 cols each)

    // staging: thread handles row tid>>1 of A and of B, 2 x 16B chunks each
    const int sRow = tid >> 1, sOff = (tid & 1) * 16;   // halfs
    const __half* aG0 = A  + (size_t)(blockM + sRow) * lda + sOff;
    const __half* bG0 = Bt + (size_t)(blockN + sRow) * ldb + sOff;
    const unsigned aS0 = smemB + (unsigned)(sRow * TS + sOff) * 2;
    const unsigned bS0 = smemB + (unsigned)(TILE_H + sRow * TS + sOff) * 2;

    auto stage = [&](int kt) {
        const unsigned so = (unsigned)(kt & 1) * (STG_H * 2);
        const __half* ag = aG0 + kt * BK;
        const __half* bg = bG0 + kt * BK;
        cp16(aS0 + so,      ag);
        cp16(aS0 + so + 16, ag + 8);
        cp16(bS0 + so,      bg);
        cp16(bS0 + so + 16, bg + 8);
        asm volatile("cp.async.commit_group;\n");
    };

    float acc[2][8][4];
#pragma unroll
    for (int mi = 0; mi < 2; mi++)
#pragma unroll
        for (int ni = 0; ni < 8; ni++)
#pragma unroll
            for (int c = 0; c < 4; c++) acc[mi][ni][c] = 0.f;

    const int T = K >> 5;
    stage(0);

    for (int kt = 0; kt < T; kt++) {
        if (kt + 1 < T) {
            stage(kt + 1);
            asm volatile("cp.async.wait_group 1;\n" ::: "memory");
        } else {
            asm volatile("cp.async.wait_group 0;\n" ::: "memory");
        }
        __syncthreads();

        const __half* as = smem + (kt & 1) * STG_H;
        const __half* bs = as + TILE_H;

#pragma unroll
        for (int ks = 0; ks < 2; ks++) {               // two k16 steps per BK=32
            const int kb = ks * 16 + 2 * (lane & 3);
            unsigned a[2][4], b[8][2];
#pragma unroll
            for (int mi = 0; mi < 2; mi++) {
                const int ar = wm * 32 + mi * 16 + (lane >> 2);
                a[mi][0] = *(const unsigned*)(as + ar * TS + kb);
                a[mi][1] = *(const unsigned*)(as + (ar + 8) * TS + kb);
                a[mi][2] = *(const unsigned*)(as + ar * TS + kb + 8);
                a[mi][3] = *(const unsigned*)(as + (ar + 8) * TS + kb + 8);
            }
#pragma unroll
            for (int ni = 0; ni < 8; ni++) {
                const int bn = wn * 64 + ni * 8 + (lane >> 2);
                b[ni][0] = *(const unsigned*)(bs + bn * TS + kb);
                b[ni][1] = *(const unsigned*)(bs + bn * TS + kb + 8);
            }
#pragma unroll
            for (int mi = 0; mi < 2; mi++)
#pragma unroll
                for (int ni = 0; ni < 8; ni++)
                    mma_f16(acc[mi][ni], a[mi], b[ni]);
        }
        __syncthreads();
    }

    // epilogue: bias + relu -> fp16 store (half2)
#pragma unroll
    for (int ni = 0; ni < 8; ni++) {
        const int col = blockN + wn * 64 + ni * 8 + 2 * (lane & 3);
        const float bb0 = bias[col];
        const float bb1 = bias[col + 1];
#pragma unroll
        for (int mi = 0; mi < 2; mi++) {
            const int row = blockM + wm * 32 + mi * 16 + (lane >> 2);
            float v0 = fmaxf(acc[mi][ni][0] + bb0, 0.f);
            float v1 = fmaxf(acc[mi][ni][1] + bb1, 0.f);
            float v2 = fmaxf(acc[mi][ni][2] + bb0, 0.f);
            float v3 = fmaxf(acc[mi][ni][3] + bb1, 0.f);
            *(__half2*)&C[(size_t)row * ldc + col]       = __floats2half2_rn(v0, v1);
            *(__half2*)&C[(size_t)(row + 8) * ldc + col] = __floats2half2_rn(v2, v3);
        }
    }
}

// ---------------------------------------------------------------------------
// Head layer 2 + tanh + Gaussian log prob; gathers fp16 Z via slot map.
// ---------------------------------------------------------------------------
__global__ void __launch_bounds__(256)
head2_logprob_kernel(const __half* __restrict__ Z,      // [M2,512] compact fp16
                     const int*   __restrict__ role_ids,
                     const float* __restrict__ actions,
                     const float* __restrict__ hW2,     // [2*512*8]
                     const float* __restrict__ hb2,
                     const float* __restrict__ logstd,
                     float* __restrict__ out)
{
    __shared__ float sW[2 * 8 * 512];  // [r][k][m]
    __shared__ float sb[16];
    __shared__ float sls[16];

    const int tid = threadIdx.x;
    for (int idx = tid; idx < 8192; idx += 256) {
        int r = idx >> 12, rem = idx & 4095, m = rem >> 3, k = rem & 7;
        sW[r * 4096 + k * 512 + m] = hW2[idx];
    }
    if (tid < 16) { sb[tid] = hb2[tid]; sls[tid] = logstd[tid]; }
    __syncthreads();

    const int warp = tid >> 5, lane = tid & 31;
    const int t = blockIdx.x * 8 + warp;

    const int role = role_ids[t];
    if (role >= 2) { if (lane == 0) out[t] = 0.f; return; }
    const int p = g_slot[t];

    const __half2* z2 = (const __half2*)(Z + (size_t)p * 512);
    const float* w = sW + role * 4096;

    float s[8];
#pragma unroll
    for (int k = 0; k < 8; k++) s[k] = 0.f;
#pragma unroll
    for (int j = 0; j < 8; j++) {
        const int i2 = lane + j * 32;            // half2 index, 256 total
        const float2 zf = __half22float2(z2[i2]);
        const int m = i2 * 2;
#pragma unroll
        for (int k = 0; k < 8; k++)
            s[k] += zf.x * w[k * 512 + m] + zf.y * w[k * 512 + m + 1];
    }
#pragma unroll
    for (int k = 0; k < 8; k++)
#pragma unroll
        for (int off = 16; off; off >>= 1)
            s[k] += __shfl_xor_sync(0xffffffffu, s[k], off);

    if (lane == 0) {
        float lp = 0.f;
#pragma unroll
        for (int k = 0; k < 8; k++) {
            float mean = tanhf(s[k] + sb[role * 8 + k]);
            float ls = sls[role * 8 + k];
            float d = (actions[t * 8 + k] - mean) * expf(-ls);
            lp += -0.5f * d * d - ls - 0.91893853320467274178f;
        }
        out[t] = lp;
    }
}

extern "C" void kernel_launch(void* const* d_in, const int* in_sizes, int n_in,
                              void* d_out, int out_size)
{
    const float* obs      = (const float*)d_in[0];
    const int*   role_ids = (const int*)  d_in[1];
    const float* actions  = (const float*)d_in[2];
    const float* W0  = (const float*)d_in[3];
    const float* b0  = (const float*)d_in[4];
    const float* W1  = (const float*)d_in[5];
    const float* b1  = (const float*)d_in[6];
    const float* W2  = (const float*)d_in[7];
    const float* b2  = (const float*)d_in[8];
    const float* hW1 = (const float*)d_in[9];
    const float* hb1 = (const float*)d_in[10];  // [2,512]
    const float* hW2 = (const float*)d_in[11];
    const float* hb2 = (const float*)d_in[12];
    const float* lsd = (const float*)d_in[13];
    float* out = (float*)d_out;

    __half *bufA, *bufB, *xpad, *zb, *wt;
    int *meta;
    cudaGetSymbolAddress((void**)&bufA, g_bufA);
    cudaGetSymbolAddress((void**)&bufB, g_bufB);
    cudaGetSymbolAddress((void**)&xpad, g_xpad);
    cudaGetSymbolAddress((void**)&zb,   g_z);
    cudaGetSymbolAddress((void**)&wt,   g_wt);
    cudaGetSymbolAddress((void**)&meta, g_meta);

    // compaction + packs
    count_roles<<<256, 128>>>(role_ids);
    scan_roles<<<1, 32>>>();
    assign_slots<<<256, 128>>>(role_ids);
    pack_x_compact<<<M_TOTAL / 8, 160>>>(obs, role_ids, xpad);
    zero_pads<<<256, 160>>>(xpad);

    dim3 tb(32, 8);
    transposeH<<<dim3(5, 32),  tb>>>(W0,  130,  1024, wt + W0T_OFF,  160);
    transposeH<<<dim3(32, 32), tb>>>(W1,  1024, 1024, wt + W1T_OFF,  1024);
    transposeH<<<dim3(32, 32), tb>>>(W2,  1024, 1024, wt + W2T_OFF,  1024);
    transposeH<<<dim3(32, 16), tb>>>(hW1,             1024, 512, wt + HW1T_OFF,             1024);
    transposeH<<<dim3(32, 16), tb>>>(hW1 + 1024*512,  1024, 512, wt + HW1T_OFF + 512*1024,  1024);

    const int GY = MMAX / BM;             // 258, blocks early-exit past M2
    dim3 block(256);
    dim3 gridMain(8, GY);                 // N=1024
    dim3 gridHead(4, GY);                 // N=512

    // shared layers on compacted rows [0, M2)
    gemm_f16<0><<<gridMain, block>>>(xpad, 160,  wt + W0T_OFF, wt + W0T_OFF, 160,  b0, b0, bufA, 1024, 160,  meta);
    gemm_f16<0><<<gridMain, block>>>(bufA, 1024, wt + W1T_OFF, wt + W1T_OFF, 1024, b1, b1, bufB, 1024, 1024, meta);
    gemm_f16<0><<<gridMain, block>>>(bufB, 1024, wt + W2T_OFF, wt + W2T_OFF, 1024, b2, b2, bufA, 1024, 1024, meta);
    // head1, single launch: role0 weights below S1, role1 above
    gemm_f16<1><<<gridHead, block>>>(bufA, 1024,
                                     wt + HW1T_OFF, wt + HW1T_OFF + 512*1024, 1024,
                                     hb1, hb1 + 512,
                                     zb, 512, 1024, meta);
    // head2 + tanh + Gaussian log-prob, gather via slot map
    head2_logprob_kernel<<<M_TOTAL / 8, 256>>>(zb, role_ids, actions,
                                               hW2, hb2, lsd, out);
}

// round 12
// speedup vs baseline: 2.0773x; 1.0369x over previous
#include <cuda_runtime.h>
#include <cuda_fp16.h>
#include <cstdint>
#include <math.h>

// ---------------------------------------------------------------------------
// ActorMultiHead — fp16 mma.sync (m16n8k16, fp32 accum) + role compaction.
// R12: ldmatrix.x4 fragment loads (issue-pressure cut), fused transpose pack.
//
//   1. compact tokens: role0 -> [0,C0), role1 -> [S1,S1+C1), S1=align128(C0)
//   2. 3 shared layers on M2 rows (~2/3 of tokens), fp16 in / fp32 acc
//   3. head1 ONE launch over [0,M2); per-block weight select at S1 boundary
//   4. head2+logprob gathers via slot map; role2 -> exact 0
// Weights pre-packed fp16 TRANSPOSED [N][K]; activations fp16 [M][K].
// ---------------------------------------------------------------------------

#define M_TOTAL  32768
#define MMAX     (M_TOTAL + 256)
#define BM 128
#define BN 128
#define BK 32
#define TS 40                        // smem row stride in halfs (80B): conflict-free
#define TILE_H (128 * TS)            // 5120 halfs per (A|B) tile
#define STG_H  (2 * TILE_H)          // 10240 halfs per stage; 2 stages = 40960B

// fp16 transposed weight pack offsets (halfs)
#define W0T_OFF  0                               // [1024][160]
#define W1T_OFF  (1024 * 160)
#define W2T_OFF  (W1T_OFF + 1024 * 1024)
#define HW1T_OFF (W2T_OFF + 1024 * 1024)         // [2][512][1024]
#define WT_TOTAL (HW1T_OFF + 2 * 512 * 1024)

// Scratch (allocation-free __device__ globals)
__device__ __half g_bufA[MMAX * 1024];
__device__ __half g_bufB[MMAX * 1024];
__device__ __half g_xpad[MMAX * 160];
__device__ __half g_z[MMAX * 512];
__device__ __half g_wt[WT_TOTAL];
__device__ int   g_slot[M_TOTAL];
__device__ int   g_cnt0[256], g_cnt1[256];
__device__ int   g_base0[256], g_base1[256];
__device__ int   g_meta[8];   // 1:M2  3:S1  6:C0  7:C1

__device__ __forceinline__ void mma_f16(float d[4], const unsigned a[4], const unsigned b[2]) {
    asm("mma.sync.aligned.m16n8k16.row.col.f32.f16.f16.f32 "
        "{%0,%1,%2,%3}, {%4,%5,%6,%7}, {%8,%9}, {%0,%1,%2,%3};\n"
        : "+f"(d[0]), "+f"(d[1]), "+f"(d[2]), "+f"(d[3])
        : "r"(a[0]), "r"(a[1]), "r"(a[2]), "r"(a[3]), "r"(b[0]), "r"(b[1]));
}

__device__ __forceinline__ void cp16(unsigned s, const void* g) {
    asm volatile("cp.async.cg.shared.global [%0], [%1], 16;\n" :: "r"(s), "l"(g));
}

__device__ __forceinline__ void ldsm_x4(unsigned &r0, unsigned &r1, unsigned &r2,
                                        unsigned &r3, unsigned a) {
    asm volatile("ldmatrix.sync.aligned.m8n8.x4.shared.b16 {%0,%1,%2,%3}, [%4];"
                 : "=r"(r0), "=r"(r1), "=r"(r2), "=r"(r3) : "r"(a));
}

// ---------------------------------------------------------------------------
// Compaction: count -> scan -> slot assignment
// ---------------------------------------------------------------------------
__global__ void count_roles(const int* __restrict__ roles)
{
    const int blk = blockIdx.x, tid = threadIdx.x;     // 256 x 128
    const int role = roles[blk * 128 + tid];
    const unsigned m0 = __ballot_sync(0xffffffffu, role == 0);
    const unsigned m1 = __ballot_sync(0xffffffffu, role == 1);
    __shared__ int c0[4], c1[4];
    if ((tid & 31) == 0) { c0[tid >> 5] = __popc(m0); c1[tid >> 5] = __popc(m1); }
    __syncthreads();
    if (tid == 0) {
        g_cnt0[blk] = c0[0] + c0[1] + c0[2] + c0[3];
        g_cnt1[blk] = c1[0] + c1[1] + c1[2] + c1[3];
    }
}

__global__ void scan_roles()
{
    if (threadIdx.x != 0) return;
    int acc = 0;
    for (int i = 0; i < 256; i++) { g_base0[i] = acc; acc += g_cnt0[i]; }
    const int C0 = acc;
    const int S1 = (C0 + 127) & ~127;
    acc = S1;
    for (int i = 0; i < 256; i++) { g_base1[i] = acc; acc += g_cnt1[i]; }
    const int C1 = acc - S1;
    const int M2 = S1 + ((C1 + 127) & ~127);
    g_meta[0] = 0;  g_meta[1] = M2;
    g_meta[2] = 0;  g_meta[3] = S1;
    g_meta[4] = S1; g_meta[5] = M2;
    g_meta[6] = C0; g_meta[7] = C1;
}

__global__ void assign_slots(const int* __restrict__ roles)
{
    const int blk = blockIdx.x, tid = threadIdx.x;
    const int t = blk * 128 + tid;
    const int role = roles[t];
    const unsigned lt = (1u << (tid & 31)) - 1u;
    const unsigned m0 = __ballot_sync(0xffffffffu, role == 0);
    const unsigned m1 = __ballot_sync(0xffffffffu, role == 1);
    __shared__ int c0[4], c1[4];
    if ((tid & 31) == 0) { c0[tid >> 5] = __popc(m0); c1[tid >> 5] = __popc(m1); }
    __syncthreads();
    int off0 = 0, off1 = 0;
    for (int w = 0; w < (tid >> 5); w++) { off0 += c0[w]; off1 += c1[w]; }
    int slot = -1;
    if (role == 0)      slot = g_base0[blk] + off0 + __popc(m0 & lt);
    else if (role == 1) slot = g_base1[blk] + off1 + __popc(m1 & lt);
    g_slot[t] = slot;
}

// xp[slot] = fp16(concat(obs, onehot), zero-pad to 160); 8 tokens per block
__global__ void pack_x_compact(const float* __restrict__ obs,
                               const int* __restrict__ roles,
                               __half* __restrict__ xp)
{
    const int k = threadIdx.x;          // 0..159
#pragma unroll
    for (int j = 0; j < 8; j++) {
        const int t = blockIdx.x * 8 + j;
        const int p = g_slot[t];
        if (p < 0) continue;
        float v = 0.f;
        if (k < 128)      v = obs[t * 128 + k];
        else if (k < 130) v = (roles[t] == (k - 128)) ? 1.f : 0.f;
        xp[p * 160 + k] = __float2half(v);
    }
}

__global__ void zero_pads(__half* __restrict__ xp)
{
    const int i = blockIdx.x;           // up to 256 pad rows
    const int C0 = g_meta[6], C1 = g_meta[7];
    const int S1 = g_meta[3], M2 = g_meta[1];
    const int p0 = S1 - C0;
    int row;
    if (i < p0) row = C0 + i;
    else if (i - p0 < M2 - (S1 + C1)) row = S1 + C1 + (i - p0);
    else return;
    xp[row * 160 + threadIdx.x] = __float2half(0.f);
}

// ---------------------------------------------------------------------------
// Fused weight transpose-pack: dst[n][k] = fp16(src[k][n]), k >= srcK -> 0.
// One launch; blockIdx selects job + tile. grid = 3232 blocks, block (32,8).
// ---------------------------------------------------------------------------
__global__ void transpose_all(const float* __restrict__ W0,
                              const float* __restrict__ W1,
                              const float* __restrict__ W2,
                              const float* __restrict__ hW1,
                              __half* __restrict__ wt)
{
    __shared__ float tile[32][33];
    int bid = blockIdx.x;
    const float* src; int srcK, srcN, dld, kT; __half* dst;
    if (bid < 160)       { src = W0;              srcK = 130;  srcN = 1024; dst = wt + W0T_OFF;              dld = 160;  kT = 5;  }
    else if (bid < 1184) { bid -= 160;  src = W1; srcK = 1024; srcN = 1024; dst = wt + W1T_OFF;              dld = 1024; kT = 32; }
    else if (bid < 2208) { bid -= 1184; src = W2; srcK = 1024; srcN = 1024; dst = wt + W2T_OFF;              dld = 1024; kT = 32; }
    else if (bid < 2720) { bid -= 2208; src = hW1;             srcK = 1024; srcN = 512; dst = wt + HW1T_OFF;             dld = 1024; kT = 32; }
    else                 { bid -= 2720; src = hW1 + 1024*512;  srcK = 1024; srcN = 512; dst = wt + HW1T_OFF + 512*1024; dld = 1024; kT = 32; }
    const int k0 = (bid % kT) * 32, n0 = (bid / kT) * 32;
    for (int i = threadIdx.y; i < 32; i += 8) {
        int k = k0 + i;
        tile[i][threadIdx.x] = (k < srcK) ? src[(size_t)k * srcN + n0 + threadIdx.x] : 0.f;
    }
    __syncthreads();
    for (int i = threadIdx.y; i < 32; i += 8)
        dst[(size_t)(n0 + i) * dld + k0 + threadIdx.x] =
            __float2half(tile[threadIdx.x][i]);
}

// ---------------------------------------------------------------------------
// fp16 GEMM: C[rows,N] = fp16(relu(A @ Bt^T + bias)); rows=[0, meta[1]).
// SPLIT=1: blocks with blockM >= meta[3] use (Bt1, bias1).
// 256 threads, 8 warps (4x2), warp tile 32x64, double-buffered cp.async,
// ldmatrix.x4 fragment loads.
// ---------------------------------------------------------------------------
template <int SPLIT>
__global__ void __launch_bounds__(256, 2)
gemm_f16(const __half* __restrict__ A, int lda,
         const __half* __restrict__ Bt0, const __half* __restrict__ Bt1, int ldb,
         const float* __restrict__ bias0, const float* __restrict__ bias1,
         __half* __restrict__ C, int ldc, int K,
         const int* __restrict__ meta)
{
    const int blockM = blockIdx.y * BM;
    if (blockM >= meta[1]) return;
    const int blockN = blockIdx.x * BN;

    const __half* Bt = Bt0;
    const float* bias = bias0;
    if (SPLIT && blockM >= meta[3]) { Bt = Bt1; bias = bias1; }

    __shared__ __half smem[2 * STG_H];   // 40960 B
    const unsigned smemB = (unsigned)__cvta_generic_to_shared(smem);

    const int tid  = threadIdx.x;
    const int lane = tid & 31;
    const int warp = tid >> 5;
    const int wm = warp >> 1;            // 4 warps along M (32 rows each)
    const int wn = warp & 1;             // 2 warps along N (64 cols each)

    // staging: thread handles row tid>>1 of A and of B, 2 x 16B chunks each
    const int sRow = tid >> 1, sOff = (tid & 1) * 16;   // halfs
    const __half* aG0 = A  + (size_t)(blockM + sRow) * lda + sOff;
    const __half* bG0 = Bt + (size_t)(blockN + sRow) * ldb + sOff;
    const unsigned aS0 = smemB + (unsigned)(sRow * TS + sOff) * 2;
    const unsigned bS0 = smemB + (unsigned)(TILE_H + sRow * TS + sOff) * 2;

    auto stage = [&](int kt) {
        const unsigned so = (unsigned)(kt & 1) * (STG_H * 2);
        const __half* ag = aG0 + kt * BK;
        const __half* bg = bG0 + kt * BK;
        cp16(aS0 + so,      ag);
        cp16(aS0 + so + 16, ag + 8);
        cp16(bS0 + so,      bg);
        cp16(bS0 + so + 16, bg + 8);
        asm volatile("cp.async.commit_group;\n");
    };

    // ldmatrix per-lane source addresses (bytes), verified against scalar map:
    // A x4: row = wm*32 + mi*16 + (lane&15), col halfs = ks*16 + ((lane>>4)<<3)
    // B x4: n   = wn*64 + np*16 + (lane&7) + ((lane>>4)<<3),
    //       col halfs = ks*16 + (((lane>>3)&1)<<3)
    const unsigned aLd = smemB +
        (unsigned)(((wm * 32 + (lane & 15)) * TS + ((lane >> 4) << 3)) * 2);
    const unsigned bLd = smemB +
        (unsigned)((TILE_H + (wn * 64 + (lane & 7) + ((lane >> 4) << 3)) * TS
                    + (((lane >> 3) & 1) << 3)) * 2);

    float acc[2][8][4];
#pragma unroll
    for (int mi = 0; mi < 2; mi++)
#pragma unroll
        for (int ni = 0; ni < 8; ni++)
#pragma unroll
            for (int c = 0; c < 4; c++) acc[mi][ni][c] = 0.f;

    const int T = K >> 5;
    stage(0);

    for (int kt = 0; kt < T; kt++) {
        if (kt + 1 < T) {
            stage(kt + 1);
            asm volatile("cp.async.wait_group 1;\n" ::: "memory");
        } else {
            asm volatile("cp.async.wait_group 0;\n" ::: "memory");
        }
        __syncthreads();

        const unsigned so = (unsigned)(kt & 1) * (STG_H * 2);

#pragma unroll
        for (int ks = 0; ks < 2; ks++) {               // two k16 steps per BK=32
            const unsigned kb = so + (unsigned)(ks * 32);   // 16 halfs = 32 B
            unsigned a[2][4], b[8][2];
            ldsm_x4(a[0][0], a[0][1], a[0][2], a[0][3], aLd + kb);
            ldsm_x4(a[1][0], a[1][1], a[1][2], a[1][3], aLd + kb + 16 * TS * 2);
#pragma unroll
            for (int np = 0; np < 4; np++)
                ldsm_x4(b[2*np][0], b[2*np][1], b[2*np+1][0], b[2*np+1][1],
                        bLd + kb + (unsigned)(np * 16 * TS * 2));
#pragma unroll
            for (int mi = 0; mi < 2; mi++)
#pragma unroll
                for (int ni = 0; ni < 8; ni++)
                    mma_f16(acc[mi][ni], a[mi], b[ni]);
        }
        __syncthreads();
    }

    // epilogue: bias + relu -> fp16 store (half2)
#pragma unroll
    for (int ni = 0; ni < 8; ni++) {
        const int col = blockN + wn * 64 + ni * 8 + 2 * (lane & 3);
        const float bb0 = bias[col];
        const float bb1 = bias[col + 1];
#pragma unroll
        for (int mi = 0; mi < 2; mi++) {
            const int row = blockM + wm * 32 + mi * 16 + (lane >> 2);
            float v0 = fmaxf(acc[mi][ni][0] + bb0, 0.f);
            float v1 = fmaxf(acc[mi][ni][1] + bb1, 0.f);
            float v2 = fmaxf(acc[mi][ni][2] + bb0, 0.f);
            float v3 = fmaxf(acc[mi][ni][3] + bb1, 0.f);
            *(__half2*)&C[(size_t)row * ldc + col]       = __floats2half2_rn(v0, v1);
            *(__half2*)&C[(size_t)(row + 8) * ldc + col] = __floats2half2_rn(v2, v3);
        }
    }
}

// ---------------------------------------------------------------------------
// Head layer 2 + tanh + Gaussian log prob; gathers fp16 Z via slot map.
// ---------------------------------------------------------------------------
__global__ void __launch_bounds__(256)
head2_logprob_kernel(const __half* __restrict__ Z,      // [M2,512] compact fp16
                     const int*   __restrict__ role_ids,
                     const float* __restrict__ actions,
                     const float* __restrict__ hW2,     // [2*512*8]
                     const float* __restrict__ hb2,
                     const float* __restrict__ logstd,
                     float* __restrict__ out)
{
    __shared__ float sW[2 * 8 * 512];  // [r][k][m]
    __shared__ float sb[16];
    __shared__ float sls[16];

    const int tid = threadIdx.x;
    for (int idx = tid; idx < 8192; idx += 256) {
        int r = idx >> 12, rem = idx & 4095, m = rem >> 3, k = rem & 7;
        sW[r * 4096 + k * 512 + m] = hW2[idx];
    }
    if (tid < 16) { sb[tid] = hb2[tid]; sls[tid] = logstd[tid]; }
    __syncthreads();

    const int warp = tid >> 5, lane = tid & 31;
    const int t = blockIdx.x * 8 + warp;

    const int role = role_ids[t];
    if (role >= 2) { if (lane == 0) out[t] = 0.f; return; }
    const int p = g_slot[t];

    const __half2* z2 = (const __half2*)(Z + (size_t)p * 512);
    const float* w = sW + role * 4096;

    float s[8];
#pragma unroll
    for (int k = 0; k < 8; k++) s[k] = 0.f;
#pragma unroll
    for (int j = 0; j < 8; j++) {
        const int i2 = lane + j * 32;            // half2 index, 256 total
        const float2 zf = __half22float2(z2[i2]);
        const int m = i2 * 2;
#pragma unroll
        for (int k = 0; k < 8; k++)
            s[k] += zf.x * w[k * 512 + m] + zf.y * w[k * 512 + m + 1];
    }
#pragma unroll
    for (int k = 0; k < 8; k++)
#pragma unroll
        for (int off = 16; off; off >>= 1)
            s[k] += __shfl_xor_sync(0xffffffffu, s[k], off);

    if (lane == 0) {
        float lp = 0.f;
#pragma unroll
        for (int k = 0; k < 8; k++) {
            float mean = tanhf(s[k] + sb[role * 8 + k]);
            float ls = sls[role * 8 + k];
            float d = (actions[t * 8 + k] - mean) * expf(-ls);
            lp += -0.5f * d * d - ls - 0.91893853320467274178f;
        }
        out[t] = lp;
    }
}

extern "C" void kernel_launch(void* const* d_in, const int* in_sizes, int n_in,
                              void* d_out, int out_size)
{
    const float* obs      = (const float*)d_in[0];
    const int*   role_ids = (const int*)  d_in[1];
    const float* actions  = (const float*)d_in[2];
    const float* W0  = (const float*)d_in[3];
    const float* b0  = (const float*)d_in[4];
    const float* W1  = (const float*)d_in[5];
    const float* b1  = (const float*)d_in[6];
    const float* W2  = (const float*)d_in[7];
    const float* b2  = (const float*)d_in[8];
    const float* hW1 = (const float*)d_in[9];
    const float* hb1 = (const float*)d_in[10];  // [2,512]
    const float* hW2 = (const float*)d_in[11];
    const float* hb2 = (const float*)d_in[12];
    const float* lsd = (const float*)d_in[13];
    float* out = (float*)d_out;

    __half *bufA, *bufB, *xpad, *zb, *wt;
    int *meta;
    cudaGetSymbolAddress((void**)&bufA, g_bufA);
    cudaGetSymbolAddress((void**)&bufB, g_bufB);
    cudaGetSymbolAddress((void**)&xpad, g_xpad);
    cudaGetSymbolAddress((void**)&zb,   g_z);
    cudaGetSymbolAddress((void**)&wt,   g_wt);
    cudaGetSymbolAddress((void**)&meta, g_meta);

    // compaction + packs
    count_roles<<<256, 128>>>(role_ids);
    scan_roles<<<1, 32>>>();
    assign_slots<<<256, 128>>>(role_ids);
    pack_x_compact<<<M_TOTAL / 8, 160>>>(obs, role_ids, xpad);
    zero_pads<<<256, 160>>>(xpad);
    transpose_all<<<3232, dim3(32, 8)>>>(W0, W1, W2, hW1, wt);

    const int GY = MMAX / BM;             // 258, blocks early-exit past M2
    dim3 block(256);
    dim3 gridMain(8, GY);                 // N=1024
    dim3 gridHead(4, GY);                 // N=512

    // shared layers on compacted rows [0, M2)
    gemm_f16<0><<<gridMain, block>>>(xpad, 160,  wt + W0T_OFF, wt + W0T_OFF, 160,  b0, b0, bufA, 1024, 160,  meta);
    gemm_f16<0><<<gridMain, block>>>(bufA, 1024, wt + W1T_OFF, wt + W1T_OFF, 1024, b1, b1, bufB, 1024, 1024, meta);
    gemm_f16<0><<<gridMain, block>>>(bufB, 1024, wt + W2T_OFF, wt + W2T_OFF, 1024, b2, b2, bufA, 1024, 1024, meta);
    // head1, single launch: role0 weights below S1, role1 above
    gemm_f16<1><<<gridHead, block>>>(bufA, 1024,
                                     wt + HW1T_OFF, wt + HW1T_OFF + 512*1024, 1024,
                                     hb1, hb1 + 512,
                                     zb, 512, 1024, meta);
    // head2 + tanh + Gaussian log-prob, gather via slot map
    head2_logprob_kernel<<<M_TOTAL / 8, 256>>>(zb, role_ids, actions,
                                               hW2, hb2, lsd, out);
}